// round 15
// baseline (speedup 1.0000x reference)
#include <cuda_runtime.h>
#include <math.h>
#include <stdint.h>

#define EMBED 768
#define NB    8
#define SEQ   1024
#define ROWS  (NB*SEQ)   // 8192
#define HID   1536
#define QB    4          // colsum q-range splits

// ---------------- scratch (__device__ globals; no allocs allowed) -----------
__device__ float g_Dp[QB][NB*12][12*EMBED];   // partial windowed row-sums of x
__device__ float g_Y[NB*12*EMBED];            // Y[bn][64m+d]
__device__ float g_u[NB*EMBED];
__device__ float g_w[NB*EMBED];
__device__ float g_wb1[NB*HID];               // b1 + w[b] @ W1
__device__ float g_xrp[(size_t)ROWS*EMBED];   // perm(tf32(x))
__device__ float g_Hp[(size_t)ROWS*HID];      // perm(tf32(gelu(..))) from GEMM2
__device__ float g_M[(size_t)ROWS*EMBED];
__device__ float g_W1P[(size_t)HID*EMBED];    // perm B frags
__device__ float g_W2P[(size_t)EMBED*HID];

// ---------------- helpers ----------------------------------------------------
__device__ __forceinline__ float f_tf32(float f) {
    uint32_t r;
    asm("cvt.rna.tf32.f32 %0, %1;" : "=r"(r) : "f"(f));
    return __uint_as_float(r);
}

// exact-GELU via Abramowitz-Stegun erf (abs err 1.5e-7)
__device__ __forceinline__ float gelu_f(float v) {
    float xs = v * 0.70710678118654752f;
    float ax = fabsf(xs);
    float t  = __frcp_rn(1.0f + 0.3275911f * ax);
    float poly = t * (0.254829592f + t * (-0.284496736f +
                 t * (1.421413741f + t * (-1.453152027f + t * 1.061405429f))));
    float erfv = 1.0f - poly * __expf(-ax * ax);
    erfv = copysignf(erfv, xs);
    return 0.5f * v * (1.0f + erfv);
}

__device__ __forceinline__ void mma_tf32(float c[4], const uint32_t a[4], const uint32_t b[2]) {
    asm volatile(
        "mma.sync.aligned.m16n8k8.row.col.f32.tf32.tf32.f32 "
        "{%0,%1,%2,%3}, {%4,%5,%6,%7}, {%8,%9}, {%0,%1,%2,%3};"
        : "+f"(c[0]), "+f"(c[1]), "+f"(c[2]), "+f"(c[3])
        : "r"(a[0]), "r"(a[1]), "r"(a[2]), "r"(a[3]), "r"(b[0]), "r"(b[1]));
}

__device__ __forceinline__ void cp16(uint32_t dst, const void* src) {
    asm volatile("cp.async.cg.shared.global [%0], [%1], 16;" :: "r"(dst), "l"(src));
}
__device__ __forceinline__ void cp_commit() {
    asm volatile("cp.async.commit_group;" ::: "memory");
}
template<int N> __device__ __forceinline__ void cp_wait() {
    asm volatile("cp.async.wait_group %0;" :: "n"(N) : "memory");
}

// ---------------- permuted-layout GEMM (round-11 proven config) --------------
#define STG 3
#define STAGEF 8192                    // floats/stage: A 4096 + B 4096
#define GEMM_SMEM (STG * STAGEF * 4)   // 98304 B

template<bool BBIAS, bool BIAS, bool GELU, bool CVT, bool PERMOUT>
__global__ __launch_bounds__(256, 2)
void gemm_p(const float* __restrict__ Ap, const float* __restrict__ Bp,
            const float* __restrict__ bias, float* __restrict__ C,
            int M, int N, int K)
{
    extern __shared__ float sm[];
    const int tid  = threadIdx.x;
    const int lane = tid & 31;
    const int warp = tid >> 5;
    const int wm = (warp & 1) * 64;
    const int wn = (warp >> 1) * 32;
    const int rowBase = blockIdx.y * 128;
    const int colBase = blockIdx.x * 128;
    const int KT8 = K >> 3;
    const int rowTile0 = blockIdx.y * 8;
    const int colTile0 = blockIdx.x * 16;
    const uint32_t smBase = (uint32_t)__cvta_generic_to_shared(sm);

    float acc[4][4][4];
    #pragma unroll
    for (int i = 0; i < 4; i++)
        #pragma unroll
        for (int j = 0; j < 4; j++)
            #pragma unroll
            for (int c = 0; c < 4; c++) acc[i][j][c] = 0.f;

    const int NC = K >> 5;

    auto stage_copy = [&](int s, int ktBase) {
        const uint32_t aB = smBase + (uint32_t)(s * STAGEF * 4);
        const uint32_t bB = aB + 16384;
        #pragma unroll
        for (int u = 0; u < 4; u++) {
            const int i  = tid + 256 * u;
            const int rt = i >> 7, kt = (i >> 5) & 3, l = i & 31;
            cp16(aB + (uint32_t)i * 16,
                 Ap + ((size_t)(rowTile0 + rt) * KT8 + ktBase + kt) * 128 + l * 4);
        }
        #pragma unroll
        for (int u = 0; u < 4; u++) {
            const int j  = tid + 256 * u;
            const int nt = j >> 6, kt = (j >> 4) & 3, p = j & 15;
            cp16(bB + (uint32_t)j * 16,
                 Bp + ((size_t)(colTile0 + nt) * KT8 + ktBase + kt) * 64 + p * 4);
        }
        cp_commit();
    };

    stage_copy(0, 0);
    stage_copy(1, 4);

    for (int j = 0; j < NC; j++) {
        if (j + 1 < NC) cp_wait<1>(); else cp_wait<0>();
        __syncthreads();

        if (j + 2 < NC) stage_copy((j + 2) % STG, (j + 2) * 4);

        const float* As_ = sm + (j % STG) * STAGEF;
        const float* Bs_ = As_ + 4096;
        #pragma unroll
        for (int kt = 0; kt < 4; kt++) {
            uint32_t afr[4][4];
            #pragma unroll
            for (int mt = 0; mt < 4; mt++) {
                const float4 v = *(const float4*)(
                    As_ + (((warp & 1) * 4 + mt) * 4 + kt) * 128 + lane * 4);
                afr[mt][0] = __float_as_uint(v.x);
                afr[mt][1] = __float_as_uint(v.y);
                afr[mt][2] = __float_as_uint(v.z);
                afr[mt][3] = __float_as_uint(v.w);
            }
            uint32_t bfr[4][2];
            #pragma unroll
            for (int nt = 0; nt < 4; nt++) {
                const float2 v = *(const float2*)(
                    Bs_ + (((warp >> 1) * 4 + nt) * 4 + kt) * 64 + lane * 2);
                bfr[nt][0] = __float_as_uint(v.x);
                bfr[nt][1] = __float_as_uint(v.y);
            }
            #pragma unroll
            for (int mt = 0; mt < 4; mt++)
                #pragma unroll
                for (int nt = 0; nt < 4; nt++)
                    mma_tf32(acc[mt][nt], afr[mt], bfr[nt]);
        }
        // no trailing barrier: next iteration's leading barrier protects the
        // stage from being overwritten.
    }
    __syncthreads();   // protect smem reuse by the PERMOUT epilogue

    const float* bp = BBIAS ? (bias + (size_t)(rowBase >> 10) * N) : bias;

    if (PERMOUT) {
        #pragma unroll
        for (int mt = 0; mt < 4; mt++) {
            const int rt_l = (warp & 1) * 4 + mt;
            #pragma unroll
            for (int nt = 0; nt < 4; nt++) {
                const int kt_l = (warp >> 1) * 4 + nt;
                const int col = colBase + wn + nt * 8 + 2 * (lane & 3);
                float v0 = acc[mt][nt][0], v1 = acc[mt][nt][1];
                float v2 = acc[mt][nt][2], v3 = acc[mt][nt][3];
                if (BIAS) {
                    float b0 = bp[col], b1v = bp[col + 1];
                    v0 += b0; v1 += b1v; v2 += b0; v3 += b1v;
                }
                if (GELU) {
                    v0 = gelu_f(v0); v1 = gelu_f(v1);
                    v2 = gelu_f(v2); v3 = gelu_f(v3);
                }
                if (CVT) {
                    v0 = f_tf32(v0); v1 = f_tf32(v1);
                    v2 = f_tf32(v2); v3 = f_tf32(v3);
                }
                float* base = sm + (rt_l * 16 + kt_l) * 128;
                const int r    = lane >> 2;
                const int cc   = 2 * (lane & 3);
                const int cp_  = cc & 3;
                const int slot = (cc < 4) ? 0 : 2;
                base[(4*r + cp_    ) * 4 + slot    ] = v0;
                base[(4*r + cp_ + 1) * 4 + slot    ] = v1;
                base[(4*r + cp_    ) * 4 + slot + 1] = v2;
                base[(4*r + cp_ + 1) * 4 + slot + 1] = v3;
            }
        }
        __syncthreads();
        #pragma unroll
        for (int u = 0; u < 16; u++) {
            const int i   = u * 256 + tid;
            const int rt  = i >> 9;
            const int idx = i & 511;
            const float4 v = ((const float4*)(sm + rt * 2048))[idx];
            ((float4*)(C + ((size_t)(rowTile0 + rt) * (N >> 3) + colTile0) * 128))[idx] = v;
        }
    } else {
        #pragma unroll
        for (int mt = 0; mt < 4; mt++) {
            const int r0 = rowBase + wm + mt * 16 + (lane >> 2);
            #pragma unroll
            for (int nt = 0; nt < 4; nt++) {
                const int col = colBase + wn + nt * 8 + 2 * (lane & 3);
                float v0 = acc[mt][nt][0], v1 = acc[mt][nt][1];
                float v2 = acc[mt][nt][2], v3 = acc[mt][nt][3];
                if (BIAS) {
                    float b0 = bp[col], b1v = bp[col + 1];
                    v0 += b0; v1 += b1v; v2 += b0; v3 += b1v;
                }
                if (GELU) {
                    v0 = gelu_f(v0); v1 = gelu_f(v1);
                    v2 = gelu_f(v2); v3 = gelu_f(v3);
                }
                if (CVT) {
                    v0 = f_tf32(v0); v1 = f_tf32(v1);
                    v2 = f_tf32(v2); v3 = f_tf32(v3);
                }
                *(float2*)(C + (size_t)r0 * N + col)       = make_float2(v0, v1);
                *(float2*)(C + (size_t)(r0 + 8) * N + col) = make_float2(v2, v3);
            }
        }
    }
}

// ---------------- perm A: [M,K] normal -> fragment tiles (+tf32) -------------
__global__ __launch_bounds__(256)
void perm_A(const float* __restrict__ in, float* __restrict__ out, int K)
{
    const size_t p4 = (size_t)blockIdx.x * 256 + threadIdx.x;
    const int KT8 = K >> 3;
    const size_t tile = p4 >> 5;
    const int l  = (int)(p4 & 31);
    const int rt = (int)(tile / KT8), kt = (int)(tile % KT8);
    const int r = rt * 16 + (l >> 2);
    const int c = kt * 8 + (l & 3);
    const float* row0 = in + (size_t)r * K;
    const float* row8 = row0 + (size_t)8 * K;
    float4 o;
    o.x = f_tf32(row0[c]);
    o.y = f_tf32(row8[c]);
    o.z = f_tf32(row0[c + 4]);
    o.w = f_tf32(row8[c + 4]);
    *(float4*)(out + p4 * 4) = o;
}

// ---------------- perm B: W[K,N] normal -> fragment tiles (+tf32) ------------
__global__ __launch_bounds__(256)
void perm_B(const float* __restrict__ W, float* __restrict__ out, int K, int N)
{
    const size_t p2 = (size_t)blockIdx.x * 256 + threadIdx.x;
    const int KT8 = K >> 3;
    const size_t tile = p2 >> 5;
    const int l  = (int)(p2 & 31);
    const int nt = (int)(tile / KT8), kt = (int)(tile % KT8);
    const int n = nt * 8 + (l >> 2);
    const int k = kt * 8 + (l & 3);
    float2 o;
    o.x = f_tf32(W[(size_t)k * N + n]);
    o.y = f_tf32(W[(size_t)(k + 4) * N + n]);
    *(float2*)(out + p2 * 2) = o;
}

// ---------------- colsum: partial windowed row-sums of x ---------------------
// D[b,n,m,k] = sum over rows q with 12q+m in [1024n, 1024n+1024).
// grid (96, QB): each block sums a quarter of the q-range into g_Dp[p].
__global__ __launch_bounds__(192)
void colsum_kernel(const float* __restrict__ x)
{
    const int bn = blockIdx.x;       // b*12+n
    const int p  = blockIdx.y;
    const int b = bn / 12, n = bn % 12;
    const int k4 = threadIdx.x * 4;
    float4 acc[12];
    #pragma unroll
    for (int m = 0; m < 12; m++) acc[m] = make_float4(0.f, 0.f, 0.f, 0.f);
    const int t0  = 1024 * n;
    const int qlo = t0 / 12;
    const int qhi = (t0 + 1023) / 12;
    const int total = qhi - qlo + 1;
    const int per = (total + QB - 1) / QB;
    const int q0 = qlo + p * per;
    int q1 = q0 + per - 1; if (q1 > qhi) q1 = qhi;
    const float* xb = x + (size_t)b * SEQ * EMBED;
    #pragma unroll 4
    for (int q = q0; q <= q1; q++) {
        const float4 v = *(const float4*)(xb + (size_t)q * EMBED + k4);
        const int base = 12 * q - t0;       // m valid iff 0 <= base+m < 1024
        #pragma unroll
        for (int m = 0; m < 12; m++) {
            const int t = base + m;
            if (t >= 0 && t < 1024) {
                acc[m].x += v.x; acc[m].y += v.y;
                acc[m].z += v.z; acc[m].w += v.w;
            }
        }
    }
    float* D = g_Dp[p][bn];
    #pragma unroll
    for (int m = 0; m < 12; m++)
        *(float4*)(D + (size_t)m * EMBED + k4) = acc[m];
}

// ---------------- mix3: Y[bn][64m+d] = sum_k D[bn][m][k] * Wv[k][64m+d] ------
// Each Wv load is amortized over 8 bn accumulators (wb1 pattern).
// grid (12 bn-groups of 8, 12 m), 128 threads = 64 d x 2 k-halves.
// D-slice for this m staged in smem (QB partials folded during load).
__global__ __launch_bounds__(128)
void mix3_kernel(const float* __restrict__ Wv)
{
    __shared__ float Dsm[8][EMBED];       // 24 KB
    __shared__ float red[2][64][8];       // 4 KB
    const int tid = threadIdx.x;
    const int bn0 = blockIdx.x * 8;
    const int m   = blockIdx.y;

    // load + fold QB partials of D[bn0..bn0+7][m][:]
    for (int i = tid; i < 8 * EMBED; i += 128) {
        const int bnl = i >> 9;            // i / 768? no: EMBED=768 not pow2
        ;
    }
    for (int i = tid; i < 8 * EMBED; i += 128) {
        const int bnl = i / EMBED;
        const int k   = i - bnl * EMBED;
        float s = 0.f;
        #pragma unroll
        for (int pp = 0; pp < QB; pp++)
            s += g_Dp[pp][bn0 + bnl][(size_t)m * EMBED + k];
        Dsm[bnl][k] = s;
    }
    __syncthreads();

    const int d  = tid & 63;
    const int kc = tid >> 6;               // 0 or 1; k in [kc*384, kc*384+384)
    const float* wp = Wv + 64 * m + d;
    float acc[8];
    #pragma unroll
    for (int b = 0; b < 8; b++) acc[b] = 0.f;
    const int k0 = kc * 384;
    #pragma unroll 4
    for (int k = k0; k < k0 + 384; k++) {
        const float w = wp[(size_t)k * EMBED];
        #pragma unroll
        for (int b = 0; b < 8; b++) acc[b] += Dsm[b][k] * w;
    }
    #pragma unroll
    for (int b = 0; b < 8; b++) red[kc][d][b] = acc[b];
    __syncthreads();
    if (kc == 0) {
        #pragma unroll
        for (int b = 0; b < 8; b++)
            g_Y[(size_t)(bn0 + b) * EMBED + 64 * m + d] =
                red[0][d][b] + red[1][d][b];
    }
}

// ---------------- ured: u[bn][d] = sum_m Y[bn][64m+d] ------------------------
__global__ __launch_bounds__(64)
void ured_kernel()
{
    const int bn = blockIdx.x;
    const int d  = threadIdx.x;
    const float* Y = g_Y + (size_t)bn * EMBED;
    float s = 0.f;
    #pragma unroll
    for (int m = 0; m < 12; m++) s += Y[64 * m + d];
    g_u[bn * 64 + d] = s;
}

// ---------------- w[b,:] = LN(u[b,:]) * g1 + beta1 ---------------------------
__global__ __launch_bounds__(256)
void ln_u_kernel(const float* __restrict__ g1, const float* __restrict__ be1)
{
    const int b   = blockIdx.x;
    const int tid = threadIdx.x;
    const float* u = g_u + b * EMBED;

    float x0 = u[tid], x1 = u[tid + 256], x2 = u[tid + 512];
    __shared__ float rs[256], rq[256];
    rs[tid] = x0 + x1 + x2;
    rq[tid] = x0 * x0 + x1 * x1 + x2 * x2;
    __syncthreads();
    for (int off = 128; off > 0; off >>= 1) {
        if (tid < off) { rs[tid] += rs[tid + off]; rq[tid] += rq[tid + off]; }
        __syncthreads();
    }
    __shared__ float s_mu, s_rstd;
    if (tid == 0) {
        float mu = rs[0] * (1.f / EMBED);
        float var = rq[0] * (1.f / EMBED) - mu * mu;
        s_mu = mu; s_rstd = rsqrtf(var + 1e-5f);
    }
    __syncthreads();
    float* w = g_w + b * EMBED;
    w[tid]       = (x0 - s_mu) * s_rstd * g1[tid]       + be1[tid];
    w[tid + 256] = (x1 - s_mu) * s_rstd * g1[tid + 256] + be1[tid + 256];
    w[tid + 512] = (x2 - s_mu) * s_rstd * g1[tid + 512] + be1[tid + 512];
}

// ---------------- wb1[b,n] = b1[n] + sum_k w[b,k] * W1[k,n] ------------------
__global__ __launch_bounds__(256)
void wb1_kernel(const float* __restrict__ W1, const float* __restrict__ b1)
{
    __shared__ float ws[NB * EMBED];           // 24 KB
    __shared__ float part[4 * 64 * NB];        // 8 KB
    const int tid = threadIdx.x;
    for (int i = tid; i < NB * EMBED; i += 256) ws[i] = g_w[i];
    __syncthreads();

    const int colL = tid & 63;
    const int col  = blockIdx.x * 64 + colL;
    const int kc   = tid >> 6;                 // 0..3, 192 k each
    float acc[NB];
    #pragma unroll
    for (int b = 0; b < NB; b++) acc[b] = 0.f;
    const int k0 = kc * 192;
    for (int k = k0; k < k0 + 192; k++) {
        const float wv = W1[(size_t)k * HID + col];
        #pragma unroll
        for (int b = 0; b < NB; b++) acc[b] += ws[b * EMBED + k] * wv;
    }
    #pragma unroll
    for (int b = 0; b < NB; b++) part[(kc * 64 + colL) * NB + b] = acc[b];
    __syncthreads();
    if (kc == 0) {
        const float bb = b1[col];
        #pragma unroll
        for (int b = 0; b < NB; b++) {
            float s = part[(colL) * NB + b] + part[(64 + colL) * NB + b]
                    + part[(128 + colL) * NB + b] + part[(192 + colL) * NB + b];
            g_wb1[b * HID + col] = s + bb;
        }
    }
}

// ---------------- out = x + LN(M)*g2 + beta2 ---------------------------------
__global__ __launch_bounds__(256)
void final_kernel(const float* __restrict__ x, const float* __restrict__ g2,
                  const float* __restrict__ be2, float* __restrict__ out)
{
    const size_t row = blockIdx.x;
    const int tid = threadIdx.x;
    const float* mr = g_M + row * EMBED;
    const float* xr = x   + row * EMBED;

    float a0 = mr[tid], a1 = mr[tid + 256], a2 = mr[tid + 512];
    __shared__ float rs[256], rq[256];
    rs[tid] = a0 + a1 + a2;
    rq[tid] = a0 * a0 + a1 * a1 + a2 * a2;
    __syncthreads();
    for (int off = 128; off > 0; off >>= 1) {
        if (tid < off) { rs[tid] += rs[tid + off]; rq[tid] += rq[tid + off]; }
        __syncthreads();
    }
    __shared__ float s_mu, s_rstd;
    if (tid == 0) {
        float mu = rs[0] * (1.f / EMBED);
        float var = rq[0] * (1.f / EMBED) - mu * mu;
        s_mu = mu; s_rstd = rsqrtf(var + 1e-5f);
    }
    __syncthreads();
    float* o = out + row * EMBED;
    o[tid]       = xr[tid]       + (a0 - s_mu) * s_rstd * g2[tid]       + be2[tid];
    o[tid + 256] = xr[tid + 256] + (a1 - s_mu) * s_rstd * g2[tid + 256] + be2[tid + 256];
    o[tid + 512] = xr[tid + 512] + (a2 - s_mu) * s_rstd * g2[tid + 512] + be2[tid + 512];
}

// ---------------------------------------------------------------------------
extern "C" void kernel_launch(void* const* d_in, const int* in_sizes, int n_in,
                              void* d_out, int out_size)
{
    const float* x   = (const float*)d_in[0];
    // d_in[1]=Wq, d_in[2]=Wk : provably dead (softmax rows sum to 1; the
    // einsum 'bnqk,bnvd->bnqd' factorizes into (sum_k attn)*(sum_v v)).
    // The V GEMM is also dead: V is only row-summed, so the sums move through
    // Wv (colsum -> mix3 -> ured).
    const float* Wv  = (const float*)d_in[3];
    const float* W1  = (const float*)d_in[4];
    const float* b1  = (const float*)d_in[5];
    const float* W2  = (const float*)d_in[6];
    const float* b2  = (const float*)d_in[7];
    const float* g1  = (const float*)d_in[8];
    const float* be1 = (const float*)d_in[9];
    const float* g2  = (const float*)d_in[10];
    const float* be2 = (const float*)d_in[11];
    float* out = (float*)d_out;

    float *pHp, *pM, *pXrp, *pW1P, *pW2P, *pWb1;
    cudaGetSymbolAddress((void**)&pHp,  g_Hp);
    cudaGetSymbolAddress((void**)&pM,   g_M);
    cudaGetSymbolAddress((void**)&pXrp, g_xrp);
    cudaGetSymbolAddress((void**)&pW1P, g_W1P);
    cudaGetSymbolAddress((void**)&pW2P, g_W2P);
    cudaGetSymbolAddress((void**)&pWb1, g_wb1);

    cudaFuncSetAttribute(gemm_p<true,true,true,true,true>,
                         cudaFuncAttributeMaxDynamicSharedMemorySize, GEMM_SMEM);
    cudaFuncSetAttribute(gemm_p<false,true,true,false,false>,
                         cudaFuncAttributeMaxDynamicSharedMemorySize, GEMM_SMEM);

    // 1) perm x (tf32 fragment tiles)
    perm_A<<<((size_t)ROWS*EMBED/4)/256, 256>>>(x, pXrp, EMBED);
    // 2) perm W1
    perm_B<<<(EMBED*HID/2)/256, 256>>>(W1, pW1P, EMBED, HID);
    // 3) partial windowed row-sums of x
    colsum_kernel<<<dim3(NB * 12, QB), 192>>>(x);
    // 4) Y = D . Wv (8-way bn amortization)            <-- profiled launch
    mix3_kernel<<<dim3(NB * 12 / 8, 12), 128>>>(Wv);
    // 5) u = reduce Y over m
    ured_kernel<<<NB * 12, 64>>>();
    // 6) perm W2
    perm_B<<<(HID*EMBED/2)/256, 256>>>(W2, pW2P, HID, EMBED);
    // 7) w[b,:] = LN(u[b,:]) * g1 + beta1
    ln_u_kernel<<<NB, 256>>>(g1, be1);
    // 8) wb1[b,:] = b1 + w[b] @ W1   (linearity: (x+w)@W1 = x@W1 + w@W1)
    wb1_kernel<<<HID/64, 256>>>(W1, b1);
    // 9) Hp = perm(tf32(gelu(x@W1 + wb1[b])))   (8192 x 1536 x 768)
    gemm_p<true,true,true,true,true><<<dim3(HID/128, ROWS/128), 256, GEMM_SMEM>>>(
        pXrp, pW1P, pWb1, pHp, ROWS, HID, EMBED);
    // 10) M = gelu(H @ W2 + b2)                 (8192 x 768 x 1536)
    gemm_p<false,true,true,false,false><<<dim3(EMBED/128, ROWS/128), 256, GEMM_SMEM>>>(
        pHp, pW2P, b2, pM, ROWS, EMBED, HID);
    // 11) out = x + LN(M) * g2 + beta2
    final_kernel<<<ROWS, 256>>>(x, g2, be2, out);
}

// round 16
// speedup vs baseline: 1.1378x; 1.1378x over previous
#include <cuda_runtime.h>
#include <math.h>
#include <stdint.h>

#define EMBED 768
#define NB    8
#define SEQ   1024
#define ROWS  (NB*SEQ)   // 8192
#define HID   1536
#define QB    4          // colsum q-range splits
#define KCN   6          // mix k-chunks (128 k each)

// ---------------- scratch (__device__ globals; no allocs allowed) -----------
__device__ float g_Dp[QB][NB*12][12*EMBED];   // partial windowed row-sums of x
__device__ float g_Yp[KCN][NB*12][EMBED];     // k-chunk partials of Y
__device__ float g_u[NB*EMBED];
__device__ float g_w[NB*EMBED];
__device__ float g_wb1[NB*HID];               // b1 + w[b] @ W1
__device__ float g_xrp[(size_t)ROWS*EMBED];   // perm(tf32(x))
__device__ float g_Hp[(size_t)ROWS*HID];      // perm(tf32(gelu(..))) from GEMM2
__device__ float g_M[(size_t)ROWS*EMBED];
__device__ float g_W1P[(size_t)HID*EMBED];    // perm B frags
__device__ float g_W2P[(size_t)EMBED*HID];

// ---------------- helpers ----------------------------------------------------
__device__ __forceinline__ float f_tf32(float f) {
    uint32_t r;
    asm("cvt.rna.tf32.f32 %0, %1;" : "=r"(r) : "f"(f));
    return __uint_as_float(r);
}

// exact-GELU via Abramowitz-Stegun erf (abs err 1.5e-7)
__device__ __forceinline__ float gelu_f(float v) {
    float xs = v * 0.70710678118654752f;
    float ax = fabsf(xs);
    float t  = __frcp_rn(1.0f + 0.3275911f * ax);
    float poly = t * (0.254829592f + t * (-0.284496736f +
                 t * (1.421413741f + t * (-1.453152027f + t * 1.061405429f))));
    float erfv = 1.0f - poly * __expf(-ax * ax);
    erfv = copysignf(erfv, xs);
    return 0.5f * v * (1.0f + erfv);
}

__device__ __forceinline__ void mma_tf32(float c[4], const uint32_t a[4], const uint32_t b[2]) {
    asm volatile(
        "mma.sync.aligned.m16n8k8.row.col.f32.tf32.tf32.f32 "
        "{%0,%1,%2,%3}, {%4,%5,%6,%7}, {%8,%9}, {%0,%1,%2,%3};"
        : "+f"(c[0]), "+f"(c[1]), "+f"(c[2]), "+f"(c[3])
        : "r"(a[0]), "r"(a[1]), "r"(a[2]), "r"(a[3]), "r"(b[0]), "r"(b[1]));
}

__device__ __forceinline__ void cp16(uint32_t dst, const void* src) {
    asm volatile("cp.async.cg.shared.global [%0], [%1], 16;" :: "r"(dst), "l"(src));
}
__device__ __forceinline__ void cp_commit() {
    asm volatile("cp.async.commit_group;" ::: "memory");
}
template<int N> __device__ __forceinline__ void cp_wait() {
    asm volatile("cp.async.wait_group %0;" :: "n"(N) : "memory");
}

// ---------------- permuted-layout GEMM (round-11 proven config) --------------
#define STG 3
#define STAGEF 8192                    // floats/stage: A 4096 + B 4096
#define GEMM_SMEM (STG * STAGEF * 4)   // 98304 B

template<bool BBIAS, bool BIAS, bool GELU, bool CVT, bool PERMOUT>
__global__ __launch_bounds__(256, 2)
void gemm_p(const float* __restrict__ Ap, const float* __restrict__ Bp,
            const float* __restrict__ bias, float* __restrict__ C,
            int M, int N, int K)
{
    extern __shared__ float sm[];
    const int tid  = threadIdx.x;
    const int lane = tid & 31;
    const int warp = tid >> 5;
    const int wm = (warp & 1) * 64;
    const int wn = (warp >> 1) * 32;
    const int rowBase = blockIdx.y * 128;
    const int colBase = blockIdx.x * 128;
    const int KT8 = K >> 3;
    const int rowTile0 = blockIdx.y * 8;
    const int colTile0 = blockIdx.x * 16;
    const uint32_t smBase = (uint32_t)__cvta_generic_to_shared(sm);

    float acc[4][4][4];
    #pragma unroll
    for (int i = 0; i < 4; i++)
        #pragma unroll
        for (int j = 0; j < 4; j++)
            #pragma unroll
            for (int c = 0; c < 4; c++) acc[i][j][c] = 0.f;

    const int NC = K >> 5;

    auto stage_copy = [&](int s, int ktBase) {
        const uint32_t aB = smBase + (uint32_t)(s * STAGEF * 4);
        const uint32_t bB = aB + 16384;
        #pragma unroll
        for (int u = 0; u < 4; u++) {
            const int i  = tid + 256 * u;
            const int rt = i >> 7, kt = (i >> 5) & 3, l = i & 31;
            cp16(aB + (uint32_t)i * 16,
                 Ap + ((size_t)(rowTile0 + rt) * KT8 + ktBase + kt) * 128 + l * 4);
        }
        #pragma unroll
        for (int u = 0; u < 4; u++) {
            const int j  = tid + 256 * u;
            const int nt = j >> 6, kt = (j >> 4) & 3, p = j & 15;
            cp16(bB + (uint32_t)j * 16,
                 Bp + ((size_t)(colTile0 + nt) * KT8 + ktBase + kt) * 64 + p * 4);
        }
        cp_commit();
    };

    stage_copy(0, 0);
    stage_copy(1, 4);

    for (int j = 0; j < NC; j++) {
        if (j + 1 < NC) cp_wait<1>(); else cp_wait<0>();
        __syncthreads();

        if (j + 2 < NC) stage_copy((j + 2) % STG, (j + 2) * 4);

        const float* As_ = sm + (j % STG) * STAGEF;
        const float* Bs_ = As_ + 4096;
        #pragma unroll
        for (int kt = 0; kt < 4; kt++) {
            uint32_t afr[4][4];
            #pragma unroll
            for (int mt = 0; mt < 4; mt++) {
                const float4 v = *(const float4*)(
                    As_ + (((warp & 1) * 4 + mt) * 4 + kt) * 128 + lane * 4);
                afr[mt][0] = __float_as_uint(v.x);
                afr[mt][1] = __float_as_uint(v.y);
                afr[mt][2] = __float_as_uint(v.z);
                afr[mt][3] = __float_as_uint(v.w);
            }
            uint32_t bfr[4][2];
            #pragma unroll
            for (int nt = 0; nt < 4; nt++) {
                const float2 v = *(const float2*)(
                    Bs_ + (((warp >> 1) * 4 + nt) * 4 + kt) * 64 + lane * 2);
                bfr[nt][0] = __float_as_uint(v.x);
                bfr[nt][1] = __float_as_uint(v.y);
            }
            #pragma unroll
            for (int mt = 0; mt < 4; mt++)
                #pragma unroll
                for (int nt = 0; nt < 4; nt++)
                    mma_tf32(acc[mt][nt], afr[mt], bfr[nt]);
        }
        // no trailing barrier: next iteration's leading barrier protects the
        // stage from being overwritten.
    }
    __syncthreads();   // protect smem reuse by the PERMOUT epilogue

    const float* bp = BBIAS ? (bias + (size_t)(rowBase >> 10) * N) : bias;

    if (PERMOUT) {
        #pragma unroll
        for (int mt = 0; mt < 4; mt++) {
            const int rt_l = (warp & 1) * 4 + mt;
            #pragma unroll
            for (int nt = 0; nt < 4; nt++) {
                const int kt_l = (warp >> 1) * 4 + nt;
                const int col = colBase + wn + nt * 8 + 2 * (lane & 3);
                float v0 = acc[mt][nt][0], v1 = acc[mt][nt][1];
                float v2 = acc[mt][nt][2], v3 = acc[mt][nt][3];
                if (BIAS) {
                    float b0 = bp[col], b1v = bp[col + 1];
                    v0 += b0; v1 += b1v; v2 += b0; v3 += b1v;
                }
                if (GELU) {
                    v0 = gelu_f(v0); v1 = gelu_f(v1);
                    v2 = gelu_f(v2); v3 = gelu_f(v3);
                }
                if (CVT) {
                    v0 = f_tf32(v0); v1 = f_tf32(v1);
                    v2 = f_tf32(v2); v3 = f_tf32(v3);
                }
                float* base = sm + (rt_l * 16 + kt_l) * 128;
                const int r    = lane >> 2;
                const int cc   = 2 * (lane & 3);
                const int cp_  = cc & 3;
                const int slot = (cc < 4) ? 0 : 2;
                base[(4*r + cp_    ) * 4 + slot    ] = v0;
                base[(4*r + cp_ + 1) * 4 + slot    ] = v1;
                base[(4*r + cp_    ) * 4 + slot + 1] = v2;
                base[(4*r + cp_ + 1) * 4 + slot + 1] = v3;
            }
        }
        __syncthreads();
        #pragma unroll
        for (int u = 0; u < 16; u++) {
            const int i   = u * 256 + tid;
            const int rt  = i >> 9;
            const int idx = i & 511;
            const float4 v = ((const float4*)(sm + rt * 2048))[idx];
            ((float4*)(C + ((size_t)(rowTile0 + rt) * (N >> 3) + colTile0) * 128))[idx] = v;
        }
    } else {
        #pragma unroll
        for (int mt = 0; mt < 4; mt++) {
            const int r0 = rowBase + wm + mt * 16 + (lane >> 2);
            #pragma unroll
            for (int nt = 0; nt < 4; nt++) {
                const int col = colBase + wn + nt * 8 + 2 * (lane & 3);
                float v0 = acc[mt][nt][0], v1 = acc[mt][nt][1];
                float v2 = acc[mt][nt][2], v3 = acc[mt][nt][3];
                if (BIAS) {
                    float b0 = bp[col], b1v = bp[col + 1];
                    v0 += b0; v1 += b1v; v2 += b0; v3 += b1v;
                }
                if (GELU) {
                    v0 = gelu_f(v0); v1 = gelu_f(v1);
                    v2 = gelu_f(v2); v3 = gelu_f(v3);
                }
                if (CVT) {
                    v0 = f_tf32(v0); v1 = f_tf32(v1);
                    v2 = f_tf32(v2); v3 = f_tf32(v3);
                }
                *(float2*)(C + (size_t)r0 * N + col)       = make_float2(v0, v1);
                *(float2*)(C + (size_t)(r0 + 8) * N + col) = make_float2(v2, v3);
            }
        }
    }
}

// ---------------- perm A: [M,K] normal -> fragment tiles (+tf32) -------------
__global__ __launch_bounds__(256)
void perm_A(const float* __restrict__ in, float* __restrict__ out, int K)
{
    const size_t p4 = (size_t)blockIdx.x * 256 + threadIdx.x;
    const int KT8 = K >> 3;
    const size_t tile = p4 >> 5;
    const int l  = (int)(p4 & 31);
    const int rt = (int)(tile / KT8), kt = (int)(tile % KT8);
    const int r = rt * 16 + (l >> 2);
    const int c = kt * 8 + (l & 3);
    const float* row0 = in + (size_t)r * K;
    const float* row8 = row0 + (size_t)8 * K;
    float4 o;
    o.x = f_tf32(row0[c]);
    o.y = f_tf32(row8[c]);
    o.z = f_tf32(row0[c + 4]);
    o.w = f_tf32(row8[c + 4]);
    *(float4*)(out + p4 * 4) = o;
}

// ---------------- perm B: W[K,N] normal -> fragment tiles (+tf32) ------------
__global__ __launch_bounds__(256)
void perm_B(const float* __restrict__ W, float* __restrict__ out, int K, int N)
{
    const size_t p2 = (size_t)blockIdx.x * 256 + threadIdx.x;
    const int KT8 = K >> 3;
    const size_t tile = p2 >> 5;
    const int l  = (int)(p2 & 31);
    const int nt = (int)(tile / KT8), kt = (int)(tile % KT8);
    const int n = nt * 8 + (l >> 2);
    const int k = kt * 8 + (l & 3);
    float2 o;
    o.x = f_tf32(W[(size_t)k * N + n]);
    o.y = f_tf32(W[(size_t)(k + 4) * N + n]);
    *(float2*)(out + p2 * 2) = o;
}

// ---------------- colsum: partial windowed row-sums of x ---------------------
// D[b,n,m,k] = sum over rows q with 12q+m in [1024n, 1024n+1024).
// grid (96, QB): each block sums a quarter of the q-range into g_Dp[p].
__global__ __launch_bounds__(192)
void colsum_kernel(const float* __restrict__ x)
{
    const int bn = blockIdx.x;       // b*12+n
    const int p  = blockIdx.y;
    const int b = bn / 12, n = bn % 12;
    const int k4 = threadIdx.x * 4;
    float4 acc[12];
    #pragma unroll
    for (int m = 0; m < 12; m++) acc[m] = make_float4(0.f, 0.f, 0.f, 0.f);
    const int t0  = 1024 * n;
    const int qlo = t0 / 12;
    const int qhi = (t0 + 1023) / 12;
    const int total = qhi - qlo + 1;
    const int per = (total + QB - 1) / QB;
    const int q0 = qlo + p * per;
    int q1 = q0 + per - 1; if (q1 > qhi) q1 = qhi;
    const float* xb = x + (size_t)b * SEQ * EMBED;
    #pragma unroll 4
    for (int q = q0; q <= q1; q++) {
        const float4 v = *(const float4*)(xb + (size_t)q * EMBED + k4);
        const int base = 12 * q - t0;       // m valid iff 0 <= base+m < 1024
        #pragma unroll
        for (int m = 0; m < 12; m++) {
            const int t = base + m;
            if (t >= 0 && t < 1024) {
                acc[m].x += v.x; acc[m].y += v.y;
                acc[m].z += v.z; acc[m].w += v.w;
            }
        }
    }
    float* D = g_Dp[p][bn];
    #pragma unroll
    for (int m = 0; m < 12; m++)
        *(float4*)(D + (size_t)m * EMBED + k4) = acc[m];
}

// ---------------- mix4: 3-D split (bn-group, m, k-chunk) ---------------------
// Yp[kc][bn][64m+d] = sum_{k in chunk kc} D[bn][m][k] * Wv[k][64m+d]
// grid (12 bn-groups of 8, 12 m, KCN k-chunks of 128) = 864 blocks, 128 thr.
// Each Wv load amortized over 8 bn; m indexes the OUTPUT (64m+d), so only the
// KCN k-chunks need deterministic partial slots (no atomics).
__global__ __launch_bounds__(128)
void mix4_kernel(const float* __restrict__ Wv)
{
    __shared__ float Dsm[8][128];          // 4 KB
    __shared__ float red[2][64][8];        // 4 KB
    const int tid = threadIdx.x;
    const int bn0 = blockIdx.x * 8;
    const int m   = blockIdx.y;
    const int kc  = blockIdx.z;
    const int kb  = kc * 128;

    // stage D[bn0..bn0+7][m][kb..kb+128), folding QB partials
    #pragma unroll
    for (int u = 0; u < 8; u++) {
        const int i   = tid + 128 * u;     // 0..1023
        const int bnl = i >> 7;
        const int kl  = i & 127;
        float s = 0.f;
        #pragma unroll
        for (int pp = 0; pp < QB; pp++)
            s += g_Dp[pp][bn0 + bnl][(size_t)m * EMBED + kb + kl];
        Dsm[bnl][kl] = s;
    }
    __syncthreads();

    const int d = tid & 63;
    const int h = tid >> 6;                // k-half: 0 or 1
    const float* wp = Wv + (size_t)(kb + h * 64) * EMBED + 64 * m + d;
    float acc[8];
    #pragma unroll
    for (int b = 0; b < 8; b++) acc[b] = 0.f;
    #pragma unroll 8
    for (int kl = 0; kl < 64; kl++) {
        const float w = wp[(size_t)kl * EMBED];
        const float* dc = &Dsm[0][h * 64 + kl];
        #pragma unroll
        for (int b = 0; b < 8; b++) acc[b] += dc[b * 128] * w;
    }
    #pragma unroll
    for (int b = 0; b < 8; b++) red[h][d][b] = acc[b];
    __syncthreads();
    if (h == 0) {
        #pragma unroll
        for (int b = 0; b < 8; b++)
            g_Yp[kc][bn0 + b][64 * m + d] = red[0][d][b] + red[1][d][b];
    }
}

// ---------------- ured: u[bn][d] = sum_m sum_kc Yp[kc][bn][64m+d] ------------
__global__ __launch_bounds__(64)
void ured_kernel()
{
    const int bn = blockIdx.x;
    const int d  = threadIdx.x;
    float s = 0.f;
    #pragma unroll
    for (int kc = 0; kc < KCN; kc++)
        #pragma unroll
        for (int m = 0; m < 12; m++)
            s += g_Yp[kc][bn][64 * m + d];
    g_u[bn * 64 + d] = s;
}

// ---------------- w[b,:] = LN(u[b,:]) * g1 + beta1 ---------------------------
__global__ __launch_bounds__(256)
void ln_u_kernel(const float* __restrict__ g1, const float* __restrict__ be1)
{
    const int b   = blockIdx.x;
    const int tid = threadIdx.x;
    const float* u = g_u + b * EMBED;

    float x0 = u[tid], x1 = u[tid + 256], x2 = u[tid + 512];
    __shared__ float rs[256], rq[256];
    rs[tid] = x0 + x1 + x2;
    rq[tid] = x0 * x0 + x1 * x1 + x2 * x2;
    __syncthreads();
    for (int off = 128; off > 0; off >>= 1) {
        if (tid < off) { rs[tid] += rs[tid + off]; rq[tid] += rq[tid + off]; }
        __syncthreads();
    }
    __shared__ float s_mu, s_rstd;
    if (tid == 0) {
        float mu = rs[0] * (1.f / EMBED);
        float var = rq[0] * (1.f / EMBED) - mu * mu;
        s_mu = mu; s_rstd = rsqrtf(var + 1e-5f);
    }
    __syncthreads();
    float* w = g_w + b * EMBED;
    w[tid]       = (x0 - s_mu) * s_rstd * g1[tid]       + be1[tid];
    w[tid + 256] = (x1 - s_mu) * s_rstd * g1[tid + 256] + be1[tid + 256];
    w[tid + 512] = (x2 - s_mu) * s_rstd * g1[tid + 512] + be1[tid + 512];
}

// ---------------- wb1[b,n] = b1[n] + sum_k w[b,k] * W1[k,n] ------------------
__global__ __launch_bounds__(256)
void wb1_kernel(const float* __restrict__ W1, const float* __restrict__ b1)
{
    __shared__ float ws[NB * EMBED];           // 24 KB
    __shared__ float part[4 * 64 * NB];        // 8 KB
    const int tid = threadIdx.x;
    for (int i = tid; i < NB * EMBED; i += 256) ws[i] = g_w[i];
    __syncthreads();

    const int colL = tid & 63;
    const int col  = blockIdx.x * 64 + colL;
    const int kc   = tid >> 6;                 // 0..3, 192 k each
    float acc[NB];
    #pragma unroll
    for (int b = 0; b < NB; b++) acc[b] = 0.f;
    const int k0 = kc * 192;
    for (int k = k0; k < k0 + 192; k++) {
        const float wv = W1[(size_t)k * HID + col];
        #pragma unroll
        for (int b = 0; b < NB; b++) acc[b] += ws[b * EMBED + k] * wv;
    }
    #pragma unroll
    for (int b = 0; b < NB; b++) part[(kc * 64 + colL) * NB + b] = acc[b];
    __syncthreads();
    if (kc == 0) {
        const float bb = b1[col];
        #pragma unroll
        for (int b = 0; b < NB; b++) {
            float s = part[(colL) * NB + b] + part[(64 + colL) * NB + b]
                    + part[(128 + colL) * NB + b] + part[(192 + colL) * NB + b];
            g_wb1[b * HID + col] = s + bb;
        }
    }
}

// ---------------- out = x + LN(M)*g2 + beta2 ---------------------------------
__global__ __launch_bounds__(256)
void final_kernel(const float* __restrict__ x, const float* __restrict__ g2,
                  const float* __restrict__ be2, float* __restrict__ out)
{
    const size_t row = blockIdx.x;
    const int tid = threadIdx.x;
    const float* mr = g_M + row * EMBED;
    const float* xr = x   + row * EMBED;

    float a0 = mr[tid], a1 = mr[tid + 256], a2 = mr[tid + 512];
    __shared__ float rs[256], rq[256];
    rs[tid] = a0 + a1 + a2;
    rq[tid] = a0 * a0 + a1 * a1 + a2 * a2;
    __syncthreads();
    for (int off = 128; off > 0; off >>= 1) {
        if (tid < off) { rs[tid] += rs[tid + off]; rq[tid] += rq[tid + off]; }
        __syncthreads();
    }
    __shared__ float s_mu, s_rstd;
    if (tid == 0) {
        float mu = rs[0] * (1.f / EMBED);
        float var = rq[0] * (1.f / EMBED) - mu * mu;
        s_mu = mu; s_rstd = rsqrtf(var + 1e-5f);
    }
    __syncthreads();
    float* o = out + row * EMBED;
    o[tid]       = xr[tid]       + (a0 - s_mu) * s_rstd * g2[tid]       + be2[tid];
    o[tid + 256] = xr[tid + 256] + (a1 - s_mu) * s_rstd * g2[tid + 256] + be2[tid + 256];
    o[tid + 512] = xr[tid + 512] + (a2 - s_mu) * s_rstd * g2[tid + 512] + be2[tid + 512];
}

// ---------------------------------------------------------------------------
extern "C" void kernel_launch(void* const* d_in, const int* in_sizes, int n_in,
                              void* d_out, int out_size)
{
    const float* x   = (const float*)d_in[0];
    // d_in[1]=Wq, d_in[2]=Wk : provably dead (softmax rows sum to 1; the
    // einsum 'bnqk,bnvd->bnqd' factorizes into (sum_k attn)*(sum_v v)).
    // The V GEMM is also dead: V is only row-summed, so the sums move through
    // Wv (colsum -> mix4 -> ured).
    const float* Wv  = (const float*)d_in[3];
    const float* W1  = (const float*)d_in[4];
    const float* b1  = (const float*)d_in[5];
    const float* W2  = (const float*)d_in[6];
    const float* b2  = (const float*)d_in[7];
    const float* g1  = (const float*)d_in[8];
    const float* be1 = (const float*)d_in[9];
    const float* g2  = (const float*)d_in[10];
    const float* be2 = (const float*)d_in[11];
    float* out = (float*)d_out;

    float *pHp, *pM, *pXrp, *pW1P, *pW2P, *pWb1;
    cudaGetSymbolAddress((void**)&pHp,  g_Hp);
    cudaGetSymbolAddress((void**)&pM,   g_M);
    cudaGetSymbolAddress((void**)&pXrp, g_xrp);
    cudaGetSymbolAddress((void**)&pW1P, g_W1P);
    cudaGetSymbolAddress((void**)&pW2P, g_W2P);
    cudaGetSymbolAddress((void**)&pWb1, g_wb1);

    cudaFuncSetAttribute(gemm_p<true,true,true,true,true>,
                         cudaFuncAttributeMaxDynamicSharedMemorySize, GEMM_SMEM);
    cudaFuncSetAttribute(gemm_p<false,true,true,false,false>,
                         cudaFuncAttributeMaxDynamicSharedMemorySize, GEMM_SMEM);

    // 1) perm x (tf32 fragment tiles)
    perm_A<<<((size_t)ROWS*EMBED/4)/256, 256>>>(x, pXrp, EMBED);
    // 2) perm W1
    perm_B<<<(EMBED*HID/2)/256, 256>>>(W1, pW1P, EMBED, HID);
    // 3) partial windowed row-sums of x
    colsum_kernel<<<dim3(NB * 12, QB), 192>>>(x);
    // 4) Yp = D . Wv, 3-D split for parallelism        <-- profiled launch
    mix4_kernel<<<dim3(NB * 12 / 8, 12, KCN), 128>>>(Wv);
    // 5) u = reduce Yp over (m, kc)
    ured_kernel<<<NB * 12, 64>>>();
    // 6) perm W2
    perm_B<<<(HID*EMBED/2)/256, 256>>>(W2, pW2P, HID, EMBED);
    // 7) w[b,:] = LN(u[b,:]) * g1 + beta1
    ln_u_kernel<<<NB, 256>>>(g1, be1);
    // 8) wb1[b,:] = b1 + w[b] @ W1   (linearity: (x+w)@W1 = x@W1 + w@W1)
    wb1_kernel<<<HID/64, 256>>>(W1, b1);
    // 9) Hp = perm(tf32(gelu(x@W1 + wb1[b])))   (8192 x 1536 x 768)
    gemm_p<true,true,true,true,true><<<dim3(HID/128, ROWS/128), 256, GEMM_SMEM>>>(
        pXrp, pW1P, pWb1, pHp, ROWS, HID, EMBED);
    // 10) M = gelu(H @ W2 + b2)                 (8192 x 768 x 1536)
    gemm_p<false,true,true,false,false><<<dim3(EMBED/128, ROWS/128), 256, GEMM_SMEM>>>(
        pHp, pW2P, b2, pM, ROWS, EMBED, HID);
    // 11) out = x + LN(M) * g2 + beta2
    final_kernel<<<ROWS, 256>>>(x, g2, be2, out);
}